// round 1
// baseline (speedup 1.0000x reference)
#include <cuda_runtime.h>

typedef unsigned long long u64;

// Problem constants
#define N_HIDDEN 14
#define WIDTH    50
#define WPAD     52    // row stride (floats) -> 208B, 16B aligned
#define IN_DIM   16
#define OUT_DIM  4

// Shared memory layout (float offsets)
#define OFF_WT0  0                       // [16][52]  transposed first layer
#define SZ_WT0   (IN_DIM * WPAD)         // 832
#define OFF_B0   (OFF_WT0 + SZ_WT0)      // 832 (50 used)
#define OFF_WTH  884                     // [14][50][52] transposed hidden
#define SZ_WTH   (N_HIDDEN * WIDTH * WPAD)   // 36400
#define OFF_BH   (OFF_WTH + SZ_WTH)      // 37284, rows of 52
#define SZ_BH    (N_HIDDEN * WPAD)       // 728
#define OFF_WTO  (OFF_BH + SZ_BH)        // 38012, [50][4]
#define SZ_WTO   (WIDTH * OUT_DIM)       // 200
#define OFF_BO   (OFF_WTO + SZ_WTO)      // 38212
#define SMEM_FLOATS (OFF_BO + 4)         // 38216
#define SMEM_BYTES  (SMEM_FLOATS * 4)    // 152864

#define THREADS 384

__device__ __forceinline__ u64 pk2(float a, float b) {
    u64 r;
    asm("mov.b64 %0, {%1, %2};" : "=l"(r) : "f"(a), "f"(b));
    return r;
}
__device__ __forceinline__ void upk(u64 v, float& a, float& b) {
    asm("mov.b64 {%0, %1}, %2;" : "=f"(a), "=f"(b) : "l"(v));
}
// d = a*b + d per 32-bit lane (packed fp32x2 FFMA)
__device__ __forceinline__ void ffma2(u64& d, u64 a, u64 b) {
    asm("fma.rn.f32x2 %0, %1, %2, %0;" : "+l"(d) : "l"(a), "l"(b));
}

// Accumulate one input scalar (broadcast-packed in hk) times one weight row
// (50 floats, j-major, 16B aligned) into 25 packed accumulators.
__device__ __forceinline__ void accum_row(u64* a, u64 hk, const float* row) {
    const ulonglong2* r2 = (const ulonglong2*)row;
#pragma unroll
    for (int q = 0; q < 12; q++) {
        ulonglong2 w = r2[q];          // LDS.128: two packed weight pairs
        ffma2(a[2 * q + 0], hk, w.x);
        ffma2(a[2 * q + 1], hk, w.y);
    }
    u64 wt = ((const u64*)row)[24];    // j = 48,49
    ffma2(a[24], hk, wt);
}

__global__ __launch_bounds__(THREADS, 1)
void mlp_kernel(const float* __restrict__ x,
                const float* __restrict__ W0, const float* __restrict__ b0,
                const float* __restrict__ Wh, const float* __restrict__ bh,
                const float* __restrict__ Wo, const float* __restrict__ bo,
                float* __restrict__ out, int n) {
    extern __shared__ float sm[];

    // ---- Stage all weights (transposed) into shared memory ----
    for (int idx = threadIdx.x; idx < WIDTH * IN_DIM; idx += blockDim.x) {
        int j = idx / IN_DIM, k = idx % IN_DIM;          // W0[j][k]
        sm[OFF_WT0 + k * WPAD + j] = W0[idx];
    }
    for (int idx = threadIdx.x; idx < WIDTH; idx += blockDim.x)
        sm[OFF_B0 + idx] = b0[idx];
    for (int idx = threadIdx.x; idx < N_HIDDEN * WIDTH * WIDTH; idx += blockDim.x) {
        int l = idx / (WIDTH * WIDTH);
        int r = idx % (WIDTH * WIDTH);
        int j = r / WIDTH, k = r % WIDTH;                // Wh[l][j][k]
        sm[OFF_WTH + (l * WIDTH + k) * WPAD + j] = Wh[idx];
    }
    for (int idx = threadIdx.x; idx < N_HIDDEN * WIDTH; idx += blockDim.x) {
        int l = idx / WIDTH, j = idx % WIDTH;
        sm[OFF_BH + l * WPAD + j] = bh[idx];
    }
    for (int idx = threadIdx.x; idx < OUT_DIM * WIDTH; idx += blockDim.x) {
        int j = idx / WIDTH, k = idx % WIDTH;            // Wo[j][k]
        sm[OFF_WTO + k * OUT_DIM + j] = Wo[idx];
    }
    for (int idx = threadIdx.x; idx < OUT_DIM; idx += blockDim.x)
        sm[OFF_BO + idx] = bo[idx];
    __syncthreads();

    const int stride = gridDim.x * blockDim.x;
    for (int i = blockIdx.x * blockDim.x + threadIdx.x; i < n; i += stride) {
        // ---- load input sample (16 floats, coalesced 4x float4) ----
        const float4* xv = (const float4*)(x + (size_t)i * IN_DIM);
        float4 x0 = xv[0], x1 = xv[1], x2 = xv[2], x3 = xv[3];
        float xin[IN_DIM] = {x0.x, x0.y, x0.z, x0.w, x1.x, x1.y, x1.z, x1.w,
                             x2.x, x2.y, x2.z, x2.w, x3.x, x3.y, x3.z, x3.w};

        u64 p[25];   // packed activations (50 values)
        u64 a[25];   // packed accumulators

        // ---- layer 0: 16 -> 50, ReLU ----
        {
            const u64* bp = (const u64*)(sm + OFF_B0);
#pragma unroll
            for (int jp = 0; jp < 25; jp++) a[jp] = bp[jp];
#pragma unroll
            for (int k = 0; k < IN_DIM; k++) {
                u64 hk = pk2(xin[k], xin[k]);
                accum_row(a, hk, sm + OFF_WT0 + k * WPAD);
            }
#pragma unroll
            for (int jp = 0; jp < 25; jp++) {
                float f0, f1;
                upk(a[jp], f0, f1);
                p[jp] = pk2(fmaxf(f0, 0.f), fmaxf(f1, 0.f));
            }
        }

        // ---- 14 hidden layers: 50 -> 50, ReLU ----
        for (int l = 0; l < N_HIDDEN; l++) {
            const float* wbase = sm + OFF_WTH + l * (WIDTH * WPAD);
            const u64* bp = (const u64*)(sm + OFF_BH + l * WPAD);
#pragma unroll
            for (int jp = 0; jp < 25; jp++) a[jp] = bp[jp];
#pragma unroll
            for (int kp = 0; kp < 25; kp++) {
                float f0, f1;
                upk(p[kp], f0, f1);
                u64 h0 = pk2(f0, f0);
                u64 h1 = pk2(f1, f1);
                accum_row(a, h0, wbase + (2 * kp + 0) * WPAD);
                accum_row(a, h1, wbase + (2 * kp + 1) * WPAD);
            }
#pragma unroll
            for (int jp = 0; jp < 25; jp++) {
                float f0, f1;
                upk(a[jp], f0, f1);
                p[jp] = pk2(fmaxf(f0, 0.f), fmaxf(f1, 0.f));
            }
        }

        // ---- output layer: 50 -> 4, no activation ----
        {
            const u64* bp = (const u64*)(sm + OFF_BO);
            u64 o0 = bp[0], o1 = bp[1];
            const ulonglong2* wo = (const ulonglong2*)(sm + OFF_WTO);
#pragma unroll
            for (int kp = 0; kp < 25; kp++) {
                float f0, f1;
                upk(p[kp], f0, f1);
                u64 h0 = pk2(f0, f0);
                u64 h1 = pk2(f1, f1);
                ulonglong2 w0 = wo[2 * kp + 0];   // row 2kp: 4 weights
                ulonglong2 w1 = wo[2 * kp + 1];   // row 2kp+1
                ffma2(o0, h0, w0.x);
                ffma2(o1, h0, w0.y);
                ffma2(o0, h1, w1.x);
                ffma2(o1, h1, w1.y);
            }
            float4 r;
            upk(o0, r.x, r.y);
            upk(o1, r.z, r.w);
            ((float4*)out)[i] = r;
        }
    }
}

extern "C" void kernel_launch(void* const* d_in, const int* in_sizes, int n_in,
                              void* d_out, int out_size) {
    const float* x  = (const float*)d_in[0];
    const float* W0 = (const float*)d_in[1];
    const float* b0 = (const float*)d_in[2];
    const float* Wh = (const float*)d_in[3];
    const float* bh = (const float*)d_in[4];
    const float* Wo = (const float*)d_in[5];
    const float* bo = (const float*)d_in[6];
    float* out = (float*)d_out;

    int n = in_sizes[0] / IN_DIM;

    int sms = 148;
    cudaDeviceGetAttribute(&sms, cudaDevAttrMultiProcessorCount, 0);

    cudaFuncSetAttribute(mlp_kernel, cudaFuncAttributeMaxDynamicSharedMemorySize,
                         SMEM_BYTES);

    mlp_kernel<<<sms, THREADS, SMEM_BYTES>>>(x, W0, b0, Wh, bh, Wo, bo, out, n);
}

// round 3
// speedup vs baseline: 2.9252x; 2.9252x over previous
#include <cuda_runtime.h>
#include <cuda_bf16.h>
#include <cstdint>

#define IN_DIM   16
#define WIDTH    50
#define OUT_DIM  4
#define NL       15            // layer0 (16->50) + 14 hidden (50->50)
#define THREADS  512
#define WARPS    (THREADS/32)

// Weights in smem: per layer, hi+lo parts, each [56 rows][64 k] bf16,
// row stride 128B, 16B-chunk swizzled by (row&7).
#define SZ_PART   7168                    // 56*128
#define SZ_LAYER  (2*SZ_PART)             // 14336
#define OFF_WH    0                       // [15][2][56][64]
#define OFF_WO    (NL*SZ_LAYER)           // 215040: [2][8 rows][64]
#define OFF_BIAS  (OFF_WO + 2*1024)       // 217088: [15][56] f32
#define OFF_BO    (OFF_BIAS + NL*56*4)    // 220448: [8] f32
#define SMEM_BYTES (OFF_BO + 32)          // 220480

__device__ __forceinline__ uint32_t smem_u32(const void* p) {
    uint32_t a;
    asm("{ .reg .u64 t; cvta.to.shared.u64 t, %1; cvt.u32.u64 %0, t; }" : "=r"(a) : "l"(p));
    return a;
}
__device__ __forceinline__ void ldsm4(uint32_t* r, uint32_t a) {
    asm volatile("ldmatrix.sync.aligned.m8n8.x4.shared.b16 {%0,%1,%2,%3}, [%4];"
                 : "=r"(r[0]), "=r"(r[1]), "=r"(r[2]), "=r"(r[3]) : "r"(a));
}
__device__ __forceinline__ void ldsm2(uint32_t* r, uint32_t a) {
    asm volatile("ldmatrix.sync.aligned.m8n8.x2.shared.b16 {%0,%1}, [%2];"
                 : "=r"(r[0]), "=r"(r[1]) : "r"(a));
}
__device__ __forceinline__ void mma_bf(float* c, const uint32_t* a, uint32_t b0, uint32_t b1) {
    asm("mma.sync.aligned.m16n8k16.row.col.f32.bf16.bf16.f32 "
        "{%0,%1,%2,%3}, {%4,%5,%6,%7}, {%8,%9}, {%0,%1,%2,%3};"
        : "+f"(c[0]), "+f"(c[1]), "+f"(c[2]), "+f"(c[3])
        : "r"(a[0]), "r"(a[1]), "r"(a[2]), "r"(a[3]), "r"(b0), "r"(b1));
}
// split two fp32 into packed bf16 hi + bf16 lo (residual)
__device__ __forceinline__ void split2(float a, float b, uint32_t& hi, uint32_t& lo) {
    __nv_bfloat162 t = __float22bfloat162_rn(make_float2(a, b));
    hi = *reinterpret_cast<uint32_t*>(&t);
    float fa = __uint_as_float(hi << 16);
    float fb = __uint_as_float(hi & 0xFFFF0000u);
    __nv_bfloat162 t2 = __float22bfloat162_rn(make_float2(a - fa, b - fb));
    lo = *reinterpret_cast<uint32_t*>(&t2);
}

// swizzled byte offset within one weight part for (row n, col k)
__device__ __host__ __forceinline__ uint32_t swoff(int n, int k) {
    return (uint32_t)(n * 128 + (((k >> 3) << 4) ^ ((n & 7) << 4)) + ((k & 7) << 1));
}

// One MMA layer: C[7][4] (bias-pre-initialized) += A * W^T over NK k-steps
template <int NK>
__device__ __forceinline__ void layer_mma(const char* sm, uint32_t sb, int layer,
                                          const uint32_t Ah[4][4], const uint32_t Al[4][4],
                                          float C[7][4], int lane) {
    const int t2 = (lane & 3) * 2;
    const int ln = lane & 7;
    const int u  = lane >> 3;
    const int nb = ((u >> 1) << 3) + ln;          // row-within-pair (x4 pattern)

    // bias init (same value for row g and g+8)
    const float* bias = (const float*)(sm + OFF_BIAS + layer * 224);
#pragma unroll
    for (int nt = 0; nt < 7; nt++) {
        float2 bv = *(const float2*)(bias + nt * 8 + t2);
        C[nt][0] = bv.x; C[nt][1] = bv.y; C[nt][2] = bv.x; C[nt][3] = bv.y;
    }

    const uint32_t hibase = sb + OFF_WH + (uint32_t)layer * SZ_LAYER;
    const uint32_t lobase = hibase + SZ_PART;
    const uint32_t swz = (uint32_t)(ln << 4);

#pragma unroll
    for (int ks = 0; ks < NK; ks++) {
        const uint32_t xh = (uint32_t)((ks * 2 + (u & 1)) << 4) ^ swz;
        uint32_t bf[14];
        // --- hi part ---
        ldsm4(bf + 0, hibase + (uint32_t)((0 * 16 + nb) * 128) + xh);
        ldsm4(bf + 4, hibase + (uint32_t)((1 * 16 + nb) * 128) + xh);
        ldsm4(bf + 8, hibase + (uint32_t)((2 * 16 + nb) * 128) + xh);
        ldsm2(bf + 12, hibase + (uint32_t)((48 + ln) * 128) + xh);
#pragma unroll
        for (int nt = 0; nt < 7; nt++) mma_bf(C[nt], Ah[ks], bf[2 * nt], bf[2 * nt + 1]);
#pragma unroll
        for (int nt = 0; nt < 7; nt++) mma_bf(C[nt], Al[ks], bf[2 * nt], bf[2 * nt + 1]);
        // --- lo part (times A-hi) ---
        ldsm4(bf + 0, lobase + (uint32_t)((0 * 16 + nb) * 128) + xh);
        ldsm4(bf + 4, lobase + (uint32_t)((1 * 16 + nb) * 128) + xh);
        ldsm4(bf + 8, lobase + (uint32_t)((2 * 16 + nb) * 128) + xh);
        ldsm2(bf + 12, lobase + (uint32_t)((48 + ln) * 128) + xh);
#pragma unroll
        for (int nt = 0; nt < 7; nt++) mma_bf(C[nt], Ah[ks], bf[2 * nt], bf[2 * nt + 1]);
    }
}

// ReLU + convert C (7 n-tiles) into next layer's A fragments (4 k-steps)
__device__ __forceinline__ void epilogue(float C[7][4], uint32_t Ah[4][4], uint32_t Al[4][4]) {
#pragma unroll
    for (int nt = 0; nt < 7; nt++)
#pragma unroll
        for (int q = 0; q < 4; q++) C[nt][q] = fmaxf(C[nt][q], 0.f);
#pragma unroll
    for (int s = 0; s < 3; s++) {
        split2(C[2*s][0],   C[2*s][1],   Ah[s][0], Al[s][0]);
        split2(C[2*s][2],   C[2*s][3],   Ah[s][1], Al[s][1]);
        split2(C[2*s+1][0], C[2*s+1][1], Ah[s][2], Al[s][2]);
        split2(C[2*s+1][2], C[2*s+1][3], Ah[s][3], Al[s][3]);
    }
    split2(C[6][0], C[6][1], Ah[3][0], Al[3][0]);
    split2(C[6][2], C[6][3], Ah[3][1], Al[3][1]);
    Ah[3][2] = Ah[3][3] = Al[3][2] = Al[3][3] = 0;
}

__global__ __launch_bounds__(THREADS, 1)
void mlp_mma_kernel(const float* __restrict__ x,
                    const float* __restrict__ W0, const float* __restrict__ b0,
                    const float* __restrict__ Wh, const float* __restrict__ bh,
                    const float* __restrict__ Wo, const float* __restrict__ bo,
                    float* __restrict__ out, int n, int ntiles, int nwarps) {
    extern __shared__ char sm[];
    const uint32_t sb = smem_u32(sm);
    const int tid  = threadIdx.x;
    const int wid  = tid >> 5;
    const int lane = tid & 31;

    // ---- stage weights: hi/lo bf16, zero-padded, swizzled ----
    for (int idx = tid; idx < NL * 56 * 64; idx += THREADS) {
        int l = idx / 3584;
        int r = idx - l * 3584;
        int nrow = r >> 6, k = r & 63;
        float f = 0.f;
        if (l == 0) { if (nrow < WIDTH && k < IN_DIM) f = W0[nrow * IN_DIM + k]; }
        else        { if (nrow < WIDTH && k < WIDTH)  f = Wh[((l - 1) * WIDTH + nrow) * WIDTH + k]; }
        __nv_bfloat16 hi = __float2bfloat16(f);
        __nv_bfloat16 lo = __float2bfloat16(f - __bfloat162float(hi));
        uint32_t so = swoff(nrow, k);
        *(__nv_bfloat16*)(sm + OFF_WH + l * SZ_LAYER + so)            = hi;
        *(__nv_bfloat16*)(sm + OFF_WH + l * SZ_LAYER + SZ_PART + so)  = lo;
    }
    for (int idx = tid; idx < 8 * 64; idx += THREADS) {
        int nrow = idx >> 6, k = idx & 63;
        float f = (nrow < OUT_DIM && k < WIDTH) ? Wo[nrow * WIDTH + k] : 0.f;
        __nv_bfloat16 hi = __float2bfloat16(f);
        __nv_bfloat16 lo = __float2bfloat16(f - __bfloat162float(hi));
        uint32_t so = swoff(nrow, k);
        *(__nv_bfloat16*)(sm + OFF_WO + so)        = hi;
        *(__nv_bfloat16*)(sm + OFF_WO + 1024 + so) = lo;
    }
    for (int idx = tid; idx < NL * 56; idx += THREADS) {
        int l = idx / 56, j = idx - l * 56;
        float f = 0.f;
        if (j < WIDTH) f = (l == 0) ? b0[j] : bh[(l - 1) * WIDTH + j];
        *(float*)(sm + OFF_BIAS + idx * 4) = f;
    }
    if (tid < 8) *(float*)(sm + OFF_BO + tid * 4) = (tid < OUT_DIM) ? bo[tid] : 0.f;
    __syncthreads();

    const int g  = lane >> 2;
    const int t2 = (lane & 3) * 2;
    const int ln = lane & 7;
    const int u  = lane >> 3;

    for (int t = blockIdx.x * WARPS + wid; t < ntiles; t += nwarps) {
        const int base = t << 4;
        uint32_t Ah[4][4], Al[4][4];
        float C[7][4];

        // ---- build layer-0 A fragments from x (K=16 exact, 1 k-step) ----
        {
            int r0 = base + g;     if (r0 > n - 1) r0 = n - 1;
            int r1 = base + g + 8; if (r1 > n - 1) r1 = n - 1;
            const float2* p0 = (const float2*)(x + (size_t)r0 * IN_DIM + t2);
            const float2* p1 = (const float2*)(x + (size_t)r1 * IN_DIM + t2);
            float2 v00 = p0[0], v01 = p0[4];
            float2 v10 = p1[0], v11 = p1[4];
            split2(v00.x, v00.y, Ah[0][0], Al[0][0]);
            split2(v10.x, v10.y, Ah[0][1], Al[0][1]);
            split2(v01.x, v01.y, Ah[0][2], Al[0][2]);
            split2(v11.x, v11.y, Ah[0][3], Al[0][3]);
        }
        layer_mma<1>(sm, sb, 0, Ah, Al, C, lane);

        // ---- 14 hidden layers ----
#pragma unroll 1
        for (int l = 1; l < NL; l++) {
            epilogue(C, Ah, Al);
            layer_mma<4>(sm, sb, l, Ah, Al, C, lane);
        }

        // ---- output layer: 50 -> 4 (single n-tile) ----
        epilogue(C, Ah, Al);
        {
            float Co[4];
            float2 bv = *(const float2*)(sm + OFF_BO + t2 * 4);
            Co[0] = bv.x; Co[1] = bv.y; Co[2] = bv.x; Co[3] = bv.y;
            const uint32_t hibase = sb + OFF_WO;
            const uint32_t lobase = hibase + 1024;
            const uint32_t swz = (uint32_t)(ln << 4);
#pragma unroll
            for (int ks = 0; ks < 4; ks++) {
                const uint32_t xh = (uint32_t)((ks * 2 + (u & 1)) << 4) ^ swz;
                uint32_t w[2];
                ldsm2(w, hibase + (uint32_t)(ln * 128) + xh);
                mma_bf(Co, Ah[ks], w[0], w[1]);
                mma_bf(Co, Al[ks], w[0], w[1]);
                ldsm2(w, lobase + (uint32_t)(ln * 128) + xh);
                mma_bf(Co, Ah[ks], w[0], w[1]);
            }
            if (t2 < OUT_DIM) {
                int r0 = base + g, r1 = base + g + 8;
                if (r0 < n) *(float2*)(out + (size_t)r0 * OUT_DIM + t2) = make_float2(Co[0], Co[1]);
                if (r1 < n) *(float2*)(out + (size_t)r1 * OUT_DIM + t2) = make_float2(Co[2], Co[3]);
            }
        }
    }
}

extern "C" void kernel_launch(void* const* d_in, const int* in_sizes, int n_in,
                              void* d_out, int out_size) {
    const float* x  = (const float*)d_in[0];
    const float* W0 = (const float*)d_in[1];
    const float* b0 = (const float*)d_in[2];
    const float* Wh = (const float*)d_in[3];
    const float* bh = (const float*)d_in[4];
    const float* Wo = (const float*)d_in[5];
    const float* bo = (const float*)d_in[6];
    float* out = (float*)d_out;

    int n = in_sizes[0] / IN_DIM;
    int ntiles = (n + 15) >> 4;

    int sms = 148;
    cudaDeviceGetAttribute(&sms, cudaDevAttrMultiProcessorCount, 0);

    cudaFuncSetAttribute(mlp_mma_kernel, cudaFuncAttributeMaxDynamicSharedMemorySize,
                         SMEM_BYTES);

    int nwarps = sms * WARPS;
    mlp_mma_kernel<<<sms, THREADS, SMEM_BYTES>>>(x, W0, b0, Wh, bh, Wo, bo, out,
                                                 n, ntiles, nwarps);
}

// round 4
// speedup vs baseline: 2.9802x; 1.0188x over previous
#include <cuda_runtime.h>
#include <cuda_bf16.h>
#include <cstdint>

#define IN_DIM   16
#define WIDTH    50
#define OUT_DIM  4
#define NL       15            // layer0 (16->50) + 14 hidden (50->50)
#define THREADS  640
#define WARPS    (THREADS/32)

// Weights in smem: per layer, hi+lo parts, each [56 rows][64 k] bf16,
// row stride 128B, 16B-chunk swizzled by (row&7).
#define SZ_PART   7168                    // 56*128
#define SZ_LAYER  (2*SZ_PART)             // 14336
#define OFF_WH    0                       // [15][2][56][64]
#define OFF_WO    (NL*SZ_LAYER)           // 215040: [2][8 rows][64]
#define OFF_BIAS  (OFF_WO + 2*1024)       // 217088: [15][56] f32
#define OFF_BO    (OFF_BIAS + NL*56*4)    // 220448: [8] f32
#define SMEM_BYTES (OFF_BO + 32)          // 220480

__device__ __forceinline__ uint32_t smem_u32(const void* p) {
    uint32_t a;
    asm("{ .reg .u64 t; cvta.to.shared.u64 t, %1; cvt.u32.u64 %0, t; }" : "=r"(a) : "l"(p));
    return a;
}
__device__ __forceinline__ void ldsm4(uint32_t* r, uint32_t a) {
    asm volatile("ldmatrix.sync.aligned.m8n8.x4.shared.b16 {%0,%1,%2,%3}, [%4];"
                 : "=r"(r[0]), "=r"(r[1]), "=r"(r[2]), "=r"(r[3]) : "r"(a));
}
__device__ __forceinline__ void ldsm2(uint32_t* r, uint32_t a) {
    asm volatile("ldmatrix.sync.aligned.m8n8.x2.shared.b16 {%0,%1}, [%2];"
                 : "=r"(r[0]), "=r"(r[1]) : "r"(a));
}
__device__ __forceinline__ void ldsm1(uint32_t& r, uint32_t a) {
    asm volatile("ldmatrix.sync.aligned.m8n8.x1.shared.b16 {%0}, [%1];"
                 : "=r"(r) : "r"(a));
}
__device__ __forceinline__ void mma_bf(float* c, const uint32_t* a, uint32_t b0, uint32_t b1) {
    asm("mma.sync.aligned.m16n8k16.row.col.f32.bf16.bf16.f32 "
        "{%0,%1,%2,%3}, {%4,%5,%6,%7}, {%8,%9}, {%0,%1,%2,%3};"
        : "+f"(c[0]), "+f"(c[1]), "+f"(c[2]), "+f"(c[3])
        : "r"(a[0]), "r"(a[1]), "r"(a[2]), "r"(a[3]), "r"(b0), "r"(b1));
}
__device__ __forceinline__ void mma_bf8(float* c, const uint32_t* a, uint32_t b0) {
    asm("mma.sync.aligned.m16n8k8.row.col.f32.bf16.bf16.f32 "
        "{%0,%1,%2,%3}, {%4,%5}, {%6}, {%0,%1,%2,%3};"
        : "+f"(c[0]), "+f"(c[1]), "+f"(c[2]), "+f"(c[3])
        : "r"(a[0]), "r"(a[1]), "r"(b0));
}
// split two fp32 into packed bf16 hi + bf16 lo (residual)
__device__ __forceinline__ void split2(float a, float b, uint32_t& hi, uint32_t& lo) {
    __nv_bfloat162 t = __float22bfloat162_rn(make_float2(a, b));
    hi = *reinterpret_cast<uint32_t*>(&t);
    float fa = __uint_as_float(hi << 16);
    float fb = __uint_as_float(hi & 0xFFFF0000u);
    __nv_bfloat162 t2 = __float22bfloat162_rn(make_float2(a - fa, b - fb));
    lo = *reinterpret_cast<uint32_t*>(&t2);
}

// swizzled byte offset within one weight part for (row n, col k)
__device__ __host__ __forceinline__ uint32_t swoff(int n, int k) {
    return (uint32_t)(n * 128 + (((k >> 3) << 4) ^ ((n & 7) << 4)) + ((k & 7) << 1));
}

// One MMA layer: C[7][4] (bias-initialized) += A * W^T.
// NK16 full k16 steps; if K8, one extra m16n8k8 step covering k 48..55.
template <int NK16, bool K8>
__device__ __forceinline__ void layer_mma(const char* sm, uint32_t sb, int layer,
                                          const uint32_t Ah[3][4], const uint32_t Al[3][4],
                                          const uint32_t* Ah3, const uint32_t* Al3,
                                          float C[7][4], int lane) {
    const int t2 = (lane & 3) * 2;
    const int ln = lane & 7;
    const int u  = lane >> 3;
    const int nb = ((u >> 1) << 3) + ln;          // row-within-pair (x4 pattern)

    // bias init (same value for row g and g+8)
    const float* bias = (const float*)(sm + OFF_BIAS + layer * 224);
#pragma unroll
    for (int nt = 0; nt < 7; nt++) {
        float2 bv = *(const float2*)(bias + nt * 8 + t2);
        C[nt][0] = bv.x; C[nt][1] = bv.y; C[nt][2] = bv.x; C[nt][3] = bv.y;
    }

    const uint32_t hibase = sb + OFF_WH + (uint32_t)layer * SZ_LAYER;
    const uint32_t lobase = hibase + SZ_PART;
    const uint32_t swz = (uint32_t)(ln << 4);

#pragma unroll
    for (int ks = 0; ks < NK16; ks++) {
        const uint32_t xh = (uint32_t)((ks * 2 + (u & 1)) << 4) ^ swz;
        uint32_t bf[14];
        // --- hi part ---
        ldsm4(bf + 0, hibase + (uint32_t)((0 * 16 + nb) * 128) + xh);
        ldsm4(bf + 4, hibase + (uint32_t)((1 * 16 + nb) * 128) + xh);
        ldsm4(bf + 8, hibase + (uint32_t)((2 * 16 + nb) * 128) + xh);
        ldsm2(bf + 12, hibase + (uint32_t)((48 + ln) * 128) + xh);
#pragma unroll
        for (int nt = 0; nt < 7; nt++) mma_bf(C[nt], Ah[ks], bf[2 * nt], bf[2 * nt + 1]);
#pragma unroll
        for (int nt = 0; nt < 7; nt++) mma_bf(C[nt], Al[ks], bf[2 * nt], bf[2 * nt + 1]);
        // --- lo part (times A-hi) ---
        ldsm4(bf + 0, lobase + (uint32_t)((0 * 16 + nb) * 128) + xh);
        ldsm4(bf + 4, lobase + (uint32_t)((1 * 16 + nb) * 128) + xh);
        ldsm4(bf + 8, lobase + (uint32_t)((2 * 16 + nb) * 128) + xh);
        ldsm2(bf + 12, lobase + (uint32_t)((48 + ln) * 128) + xh);
#pragma unroll
        for (int nt = 0; nt < 7; nt++) mma_bf(C[nt], Ah[ks], bf[2 * nt], bf[2 * nt + 1]);
    }

    if (K8) {
        // k8 step covering k = 48..55 (chunk 6). B frag: one reg per n-tile.
        // ldsm4 #1: rows 0-31 (tiles 0-3); #2: rows 32-63 (tiles 4-6 + pad).
        const uint32_t x8 = (uint32_t)(96u ^ (uint32_t)(ln << 4));
        uint32_t b8[8];
        ldsm4(b8 + 0, hibase + (uint32_t)(lane * 128) + x8);
        ldsm4(b8 + 4, hibase + (uint32_t)((32 + lane) * 128) + x8);
#pragma unroll
        for (int nt = 0; nt < 7; nt++) mma_bf8(C[nt], Ah3, b8[nt]);
#pragma unroll
        for (int nt = 0; nt < 7; nt++) mma_bf8(C[nt], Al3, b8[nt]);
        ldsm4(b8 + 0, lobase + (uint32_t)(lane * 128) + x8);
        ldsm4(b8 + 4, lobase + (uint32_t)((32 + lane) * 128) + x8);
#pragma unroll
        for (int nt = 0; nt < 7; nt++) mma_bf8(C[nt], Ah3, b8[nt]);
    }
}

// ReLU + convert C (7 n-tiles) into next layer's A fragments (3 k16 + 1 k8)
__device__ __forceinline__ void epilogue(float C[7][4], uint32_t Ah[3][4], uint32_t Al[3][4],
                                         uint32_t* Ah3, uint32_t* Al3) {
#pragma unroll
    for (int nt = 0; nt < 7; nt++)
#pragma unroll
        for (int q = 0; q < 4; q++) C[nt][q] = fmaxf(C[nt][q], 0.f);
#pragma unroll
    for (int s = 0; s < 3; s++) {
        split2(C[2*s][0],   C[2*s][1],   Ah[s][0], Al[s][0]);
        split2(C[2*s][2],   C[2*s][3],   Ah[s][1], Al[s][1]);
        split2(C[2*s+1][0], C[2*s+1][1], Ah[s][2], Al[s][2]);
        split2(C[2*s+1][2], C[2*s+1][3], Ah[s][3], Al[s][3]);
    }
    split2(C[6][0], C[6][1], Ah3[0], Al3[0]);
    split2(C[6][2], C[6][3], Ah3[1], Al3[1]);
}

__global__ __launch_bounds__(THREADS, 1)
void mlp_mma_kernel(const float* __restrict__ x,
                    const float* __restrict__ W0, const float* __restrict__ b0,
                    const float* __restrict__ Wh, const float* __restrict__ bh,
                    const float* __restrict__ Wo, const float* __restrict__ bo,
                    float* __restrict__ out, int n, int ntiles, int nwarps) {
    extern __shared__ char sm[];
    const uint32_t sb = smem_u32(sm);
    const int tid  = threadIdx.x;
    const int wid  = tid >> 5;
    const int lane = tid & 31;

    // ---- stage weights: hi/lo bf16, zero-padded, swizzled ----
    for (int idx = tid; idx < NL * 56 * 64; idx += THREADS) {
        int l = idx / 3584;
        int r = idx - l * 3584;
        int nrow = r >> 6, k = r & 63;
        float f = 0.f;
        if (l == 0) { if (nrow < WIDTH && k < IN_DIM) f = W0[nrow * IN_DIM + k]; }
        else        { if (nrow < WIDTH && k < WIDTH)  f = Wh[((l - 1) * WIDTH + nrow) * WIDTH + k]; }
        __nv_bfloat16 hi = __float2bfloat16(f);
        __nv_bfloat16 lo = __float2bfloat16(f - __bfloat162float(hi));
        uint32_t so = swoff(nrow, k);
        *(__nv_bfloat16*)(sm + OFF_WH + l * SZ_LAYER + so)            = hi;
        *(__nv_bfloat16*)(sm + OFF_WH + l * SZ_LAYER + SZ_PART + so)  = lo;
    }
    for (int idx = tid; idx < 8 * 64; idx += THREADS) {
        int nrow = idx >> 6, k = idx & 63;
        float f = (nrow < OUT_DIM && k < WIDTH) ? Wo[nrow * WIDTH + k] : 0.f;
        __nv_bfloat16 hi = __float2bfloat16(f);
        __nv_bfloat16 lo = __float2bfloat16(f - __bfloat162float(hi));
        uint32_t so = swoff(nrow, k);
        *(__nv_bfloat16*)(sm + OFF_WO + so)        = hi;
        *(__nv_bfloat16*)(sm + OFF_WO + 1024 + so) = lo;
    }
    for (int idx = tid; idx < NL * 56; idx += THREADS) {
        int l = idx / 56, j = idx - l * 56;
        float f = 0.f;
        if (j < WIDTH) f = (l == 0) ? b0[j] : bh[(l - 1) * WIDTH + j];
        *(float*)(sm + OFF_BIAS + idx * 4) = f;
    }
    if (tid < 8) *(float*)(sm + OFF_BO + tid * 4) = (tid < OUT_DIM) ? bo[tid] : 0.f;
    __syncthreads();

    const int g  = lane >> 2;
    const int t2 = (lane & 3) * 2;
    const int ln = lane & 7;
    const int u  = lane >> 3;

    for (int t = blockIdx.x * WARPS + wid; t < ntiles; t += nwarps) {
        const int base = t << 4;
        uint32_t Ah[3][4], Al[3][4], Ah3[2], Al3[2];
        float C[7][4];

        // ---- build layer-0 A fragments from x (K=16 exact, 1 k-step) ----
        {
            int r0 = base + g;     if (r0 > n - 1) r0 = n - 1;
            int r1 = base + g + 8; if (r1 > n - 1) r1 = n - 1;
            const float2* p0 = (const float2*)(x + (size_t)r0 * IN_DIM + t2);
            const float2* p1 = (const float2*)(x + (size_t)r1 * IN_DIM + t2);
            float2 v00 = p0[0], v01 = p0[4];
            float2 v10 = p1[0], v11 = p1[4];
            split2(v00.x, v00.y, Ah[0][0], Al[0][0]);
            split2(v10.x, v10.y, Ah[0][1], Al[0][1]);
            split2(v01.x, v01.y, Ah[0][2], Al[0][2]);
            split2(v11.x, v11.y, Ah[0][3], Al[0][3]);
        }
        layer_mma<1, false>(sm, sb, 0, Ah, Al, Ah3, Al3, C, lane);

        // ---- 14 hidden layers (K = 56: 3x k16 + 1x k8) ----
#pragma unroll 1
        for (int l = 1; l < NL; l++) {
            epilogue(C, Ah, Al, Ah3, Al3);
            layer_mma<3, true>(sm, sb, l, Ah, Al, Ah3, Al3, C, lane);
        }

        // ---- output layer: 50 -> 4 (single n-tile, 3x k16 + 1x k8) ----
        epilogue(C, Ah, Al, Ah3, Al3);
        {
            float Co[4];
            float2 bv = *(const float2*)(sm + OFF_BO + t2 * 4);
            Co[0] = bv.x; Co[1] = bv.y; Co[2] = bv.x; Co[3] = bv.y;
            const uint32_t hibase = sb + OFF_WO;
            const uint32_t lobase = hibase + 1024;
            const uint32_t swz = (uint32_t)(ln << 4);
#pragma unroll
            for (int ks = 0; ks < 3; ks++) {
                const uint32_t xh = (uint32_t)((ks * 2 + (u & 1)) << 4) ^ swz;
                uint32_t w[2];
                ldsm2(w, hibase + (uint32_t)(ln * 128) + xh);
                mma_bf(Co, Ah[ks], w[0], w[1]);
                mma_bf(Co, Al[ks], w[0], w[1]);
                ldsm2(w, lobase + (uint32_t)(ln * 128) + xh);
                mma_bf(Co, Ah[ks], w[0], w[1]);
            }
            {
                const uint32_t x8 = (uint32_t)(96u ^ (uint32_t)(ln << 4));
                uint32_t w0;
                ldsm1(w0, hibase + (uint32_t)(ln * 128) + x8);
                mma_bf8(Co, Ah3, w0);
                mma_bf8(Co, Al3, w0);
                ldsm1(w0, lobase + (uint32_t)(ln * 128) + x8);
                mma_bf8(Co, Ah3, w0);
            }
            if (t2 < OUT_DIM) {
                int r0 = base + g, r1 = base + g + 8;
                if (r0 < n) *(float2*)(out + (size_t)r0 * OUT_DIM + t2) = make_float2(Co[0], Co[1]);
                if (r1 < n) *(float2*)(out + (size_t)r1 * OUT_DIM + t2) = make_float2(Co[2], Co[3]);
            }
        }
    }
}

extern "C" void kernel_launch(void* const* d_in, const int* in_sizes, int n_in,
                              void* d_out, int out_size) {
    const float* x  = (const float*)d_in[0];
    const float* W0 = (const float*)d_in[1];
    const float* b0 = (const float*)d_in[2];
    const float* Wh = (const float*)d_in[3];
    const float* bh = (const float*)d_in[4];
    const float* Wo = (const float*)d_in[5];
    const float* bo = (const float*)d_in[6];
    float* out = (float*)d_out;

    int n = in_sizes[0] / IN_DIM;
    int ntiles = (n + 15) >> 4;

    int sms = 148;
    cudaDeviceGetAttribute(&sms, cudaDevAttrMultiProcessorCount, 0);

    cudaFuncSetAttribute(mlp_mma_kernel, cudaFuncAttributeMaxDynamicSharedMemorySize,
                         SMEM_BYTES);

    int nwarps = sms * WARPS;
    mlp_mma_kernel<<<sms, THREADS, SMEM_BYTES>>>(x, W0, b0, Wh, bh, Wo, bo, out,
                                                 n, ntiles, nwarps);
}

// round 5
// speedup vs baseline: 3.3700x; 1.1308x over previous
#include <cuda_runtime.h>
#include <cuda_bf16.h>
#include <cstdint>

#define IN_DIM   16
#define WIDTH    50
#define OUT_DIM  4
#define NL       15            // layer0 (16->50) + 14 hidden (50->50)
#define THREADS  640
#define WARPS    (THREADS/32)

// Weights in smem: per layer, hi+lo parts, each [56 rows][64 k] bf16,
// row stride 128B, 16B-chunk swizzled by (row&7).
// hi part chunk 6 (cols 48-55) holds the MERGED TAIL: [bh48 bh49 bh48 bh49 bl48 bl49 0 0]
// chunk 7 and all lo-part cols >= 48 are zero.
#define SZ_PART   7168                    // 56*128
#define SZ_LAYER  (2*SZ_PART)             // 14336
#define OFF_WH    0                       // [15][2][56][64]
#define OFF_WO    (NL*SZ_LAYER)           // 215040: [2][8 rows][64]
#define OFF_BIAS  (OFF_WO + 2*1024)       // 217088: [15][56] f32
#define OFF_BO    (OFF_BIAS + NL*56*4)    // 220448: [8] f32
#define SMEM_BYTES (OFF_BO + 32)          // 220480

__device__ __forceinline__ uint32_t smem_u32(const void* p) {
    uint32_t a;
    asm("{ .reg .u64 t; cvta.to.shared.u64 t, %1; cvt.u32.u64 %0, t; }" : "=r"(a) : "l"(p));
    return a;
}
__device__ __forceinline__ void ldsm4(uint32_t* r, uint32_t a) {
    asm volatile("ldmatrix.sync.aligned.m8n8.x4.shared.b16 {%0,%1,%2,%3}, [%4];"
                 : "=r"(r[0]), "=r"(r[1]), "=r"(r[2]), "=r"(r[3]) : "r"(a));
}
__device__ __forceinline__ void ldsm2(uint32_t* r, uint32_t a) {
    asm volatile("ldmatrix.sync.aligned.m8n8.x2.shared.b16 {%0,%1}, [%2];"
                 : "=r"(r[0]), "=r"(r[1]) : "r"(a));
}
__device__ __forceinline__ void ldsm1(uint32_t& r, uint32_t a) {
    asm volatile("ldmatrix.sync.aligned.m8n8.x1.shared.b16 {%0}, [%1];"
                 : "=r"(r) : "r"(a));
}
__device__ __forceinline__ void mma_bf(float* c, const uint32_t* a, uint32_t b0, uint32_t b1) {
    asm("mma.sync.aligned.m16n8k16.row.col.f32.bf16.bf16.f32 "
        "{%0,%1,%2,%3}, {%4,%5,%6,%7}, {%8,%9}, {%0,%1,%2,%3};"
        : "+f"(c[0]), "+f"(c[1]), "+f"(c[2]), "+f"(c[3])
        : "r"(a[0]), "r"(a[1]), "r"(a[2]), "r"(a[3]), "r"(b0), "r"(b1));
}
__device__ __forceinline__ void mma_bf8(float* c, uint32_t a0, uint32_t a1, uint32_t b0) {
    asm("mma.sync.aligned.m16n8k8.row.col.f32.bf16.bf16.f32 "
        "{%0,%1,%2,%3}, {%4,%5}, {%6}, {%0,%1,%2,%3};"
        : "+f"(c[0]), "+f"(c[1]), "+f"(c[2]), "+f"(c[3])
        : "r"(a0), "r"(a1), "r"(b0));
}
// split two fp32 into packed bf16 hi + bf16 lo (residual)
__device__ __forceinline__ void split2(float a, float b, uint32_t& hi, uint32_t& lo) {
    __nv_bfloat162 t = __float22bfloat162_rn(make_float2(a, b));
    hi = *reinterpret_cast<uint32_t*>(&t);
    float fa = __uint_as_float(hi << 16);
    float fb = __uint_as_float(hi & 0xFFFF0000u);
    __nv_bfloat162 t2 = __float22bfloat162_rn(make_float2(a - fa, b - fb));
    lo = *reinterpret_cast<uint32_t*>(&t2);
}

// swizzled byte offset within one weight part for (row n, col k)
__device__ __host__ __forceinline__ uint32_t swoff(int n, int k) {
    return (uint32_t)(n * 128 + (((k >> 3) << 4) ^ ((n & 7) << 4)) + ((k & 7) << 1));
}

// Build the merged-tail A fragment: k-cols [ah|al|ah|0] from quad-lane-0's
// C[6] splits (cols 48,49). 4 shuffles + selects.
__device__ __forceinline__ void make_tail(const uint32_t Ah3[2], const uint32_t Al3[2],
                                          int lane, uint32_t& a0, uint32_t& a1) {
    const int src = lane & 28;
    uint32_t ah0 = __shfl_sync(0xFFFFFFFFu, Ah3[0], src);
    uint32_t ah1 = __shfl_sync(0xFFFFFFFFu, Ah3[1], src);
    uint32_t al0 = __shfl_sync(0xFFFFFFFFu, Al3[0], src);
    uint32_t al1 = __shfl_sync(0xFFFFFFFFu, Al3[1], src);
    const int t = lane & 3;
    a0 = (t == 3) ? 0u : (t == 1 ? al0 : ah0);
    a1 = (t == 3) ? 0u : (t == 1 ? al1 : ah1);
}

// One MMA layer: C[7][4] (bias-initialized) += A * W^T.
// NK16 full k16 steps (cols 0..16*NK16); TAIL: one merged k8 step (cols 48,49 x 3 products).
template <int NK16, bool TAIL>
__device__ __forceinline__ void layer_mma(const char* sm, uint32_t sb, int layer,
                                          const uint32_t Ah[3][4], const uint32_t Al[3][4],
                                          uint32_t at0, uint32_t at1,
                                          float C[7][4], int lane) {
    const int t2 = (lane & 3) * 2;
    const int ln = lane & 7;
    const int u  = lane >> 3;
    const int nb = ((u >> 1) << 3) + ln;          // row-within-pair (x4 pattern)

    // bias init (same value for row g and g+8)
    const float* bias = (const float*)(sm + OFF_BIAS + layer * 224);
#pragma unroll
    for (int nt = 0; nt < 7; nt++) {
        float2 bv = *(const float2*)(bias + nt * 8 + t2);
        C[nt][0] = bv.x; C[nt][1] = bv.y; C[nt][2] = bv.x; C[nt][3] = bv.y;
    }

    const uint32_t hibase = sb + OFF_WH + (uint32_t)layer * SZ_LAYER;
    const uint32_t lobase = hibase + SZ_PART;
    const uint32_t swz = (uint32_t)(ln << 4);

#pragma unroll
    for (int ks = 0; ks < NK16; ks++) {
        const uint32_t xh = (uint32_t)((ks * 2 + (u & 1)) << 4) ^ swz;
        uint32_t bf[14];
        // --- hi part ---
        ldsm4(bf + 0, hibase + (uint32_t)((0 * 16 + nb) * 128) + xh);
        ldsm4(bf + 4, hibase + (uint32_t)((1 * 16 + nb) * 128) + xh);
        ldsm4(bf + 8, hibase + (uint32_t)((2 * 16 + nb) * 128) + xh);
        ldsm2(bf + 12, hibase + (uint32_t)((48 + ln) * 128) + xh);
#pragma unroll
        for (int nt = 0; nt < 7; nt++) mma_bf(C[nt], Ah[ks], bf[2 * nt], bf[2 * nt + 1]);
#pragma unroll
        for (int nt = 0; nt < 7; nt++) mma_bf(C[nt], Al[ks], bf[2 * nt], bf[2 * nt + 1]);
        // --- lo part (times A-hi) ---
        ldsm4(bf + 0, lobase + (uint32_t)((0 * 16 + nb) * 128) + xh);
        ldsm4(bf + 4, lobase + (uint32_t)((1 * 16 + nb) * 128) + xh);
        ldsm4(bf + 8, lobase + (uint32_t)((2 * 16 + nb) * 128) + xh);
        ldsm2(bf + 12, lobase + (uint32_t)((48 + ln) * 128) + xh);
#pragma unroll
        for (int nt = 0; nt < 7; nt++) mma_bf(C[nt], Ah[ks], bf[2 * nt], bf[2 * nt + 1]);
    }

    if (TAIL) {
        // single merged k8 step (chunk 6 of hi part holds the mixed B tail)
        const uint32_t x8 = (uint32_t)(96u ^ (uint32_t)(ln << 4));
        uint32_t b8[8];
        ldsm4(b8 + 0, hibase + (uint32_t)(lane * 128) + x8);
        ldsm4(b8 + 4, hibase + (uint32_t)((32 + lane) * 128) + x8);
#pragma unroll
        for (int nt = 0; nt < 7; nt++) mma_bf8(C[nt], at0, at1, b8[nt]);
    }
}

// ReLU + convert C (7 n-tiles) into next layer's A fragments (3 k16 + tail pair)
__device__ __forceinline__ void epilogue(float C[7][4], uint32_t Ah[3][4], uint32_t Al[3][4],
                                         uint32_t* Ah3, uint32_t* Al3) {
#pragma unroll
    for (int nt = 0; nt < 7; nt++)
#pragma unroll
        for (int q = 0; q < 4; q++) C[nt][q] = fmaxf(C[nt][q], 0.f);
#pragma unroll
    for (int s = 0; s < 3; s++) {
        split2(C[2*s][0],   C[2*s][1],   Ah[s][0], Al[s][0]);
        split2(C[2*s][2],   C[2*s][3],   Ah[s][1], Al[s][1]);
        split2(C[2*s+1][0], C[2*s+1][1], Ah[s][2], Al[s][2]);
        split2(C[2*s+1][2], C[2*s+1][3], Ah[s][3], Al[s][3]);
    }
    split2(C[6][0], C[6][1], Ah3[0], Al3[0]);
    split2(C[6][2], C[6][3], Ah3[1], Al3[1]);
}

__global__ __launch_bounds__(THREADS, 1)
void mlp_mma_kernel(const float* __restrict__ x,
                    const float* __restrict__ W0, const float* __restrict__ b0,
                    const float* __restrict__ Wh, const float* __restrict__ bh,
                    const float* __restrict__ Wo, const float* __restrict__ bo,
                    float* __restrict__ out, int n, int ntiles, int nwarps) {
    extern __shared__ char sm[];
    const uint32_t sb = smem_u32(sm);
    const int tid  = threadIdx.x;
    const int wid  = tid >> 5;
    const int lane = tid & 31;

    // ---- stage weights: hi/lo bf16, zero-padded, swizzled; merged tail in hi chunk 6 ----
    for (int idx = tid; idx < NL * 56 * 64; idx += THREADS) {
        int l = idx / 3584;
        int r = idx - l * 3584;
        int nrow = r >> 6, k = r & 63;
        int Kreal = (l == 0) ? IN_DIM : WIDTH;
        __nv_bfloat16 hv, lv;
        if (k < 48) {
            float f = 0.f;
            if (nrow < WIDTH && k < Kreal)
                f = (l == 0) ? W0[nrow * IN_DIM + k] : Wh[((l - 1) * WIDTH + nrow) * WIDTH + k];
            hv = __float2bfloat16(f);
            lv = __float2bfloat16(f - __bfloat162float(hv));
        } else {
            int m = k - 48, p = m >> 1, c = m & 1;
            int kk = 48 + c;
            float f = 0.f;
            if (l > 0 && nrow < WIDTH && kk < Kreal)
                f = Wh[((l - 1) * WIDTH + nrow) * WIDTH + kk];
            __nv_bfloat16 fh = __float2bfloat16(f);
            __nv_bfloat16 fl = __float2bfloat16(f - __bfloat162float(fh));
            hv = (p < 2) ? fh : (p == 2 ? fl : __float2bfloat16(0.f));
            lv = __float2bfloat16(0.f);
        }
        uint32_t so = swoff(nrow, k);
        *(__nv_bfloat16*)(sm + OFF_WH + l * SZ_LAYER + so)           = hv;
        *(__nv_bfloat16*)(sm + OFF_WH + l * SZ_LAYER + SZ_PART + so) = lv;
    }
    for (int idx = tid; idx < 8 * 64; idx += THREADS) {
        int nrow = idx >> 6, k = idx & 63;
        __nv_bfloat16 hv, lv;
        if (k < 48) {
            float f = (nrow < OUT_DIM) ? Wo[nrow * WIDTH + k] : 0.f;
            hv = __float2bfloat16(f);
            lv = __float2bfloat16(f - __bfloat162float(hv));
        } else {
            int m = k - 48, p = m >> 1, c = m & 1;
            int kk = 48 + c;
            float f = (nrow < OUT_DIM && kk < WIDTH) ? Wo[nrow * WIDTH + kk] : 0.f;
            __nv_bfloat16 fh = __float2bfloat16(f);
            __nv_bfloat16 fl = __float2bfloat16(f - __bfloat162float(fh));
            hv = (p < 2) ? fh : (p == 2 ? fl : __float2bfloat16(0.f));
            lv = __float2bfloat16(0.f);
        }
        uint32_t so = swoff(nrow, k);
        *(__nv_bfloat16*)(sm + OFF_WO + so)        = hv;
        *(__nv_bfloat16*)(sm + OFF_WO + 1024 + so) = lv;
    }
    for (int idx = tid; idx < NL * 56; idx += THREADS) {
        int l = idx / 56, j = idx - l * 56;
        float f = 0.f;
        if (j < WIDTH) f = (l == 0) ? b0[j] : bh[(l - 1) * WIDTH + j];
        *(float*)(sm + OFF_BIAS + idx * 4) = f;
    }
    if (tid < 8) *(float*)(sm + OFF_BO + tid * 4) = (tid < OUT_DIM) ? bo[tid] : 0.f;
    __syncthreads();

    const int g  = lane >> 2;
    const int t2 = (lane & 3) * 2;
    const int ln = lane & 7;
    const int u  = lane >> 3;

    for (int t = blockIdx.x * WARPS + wid; t < ntiles; t += nwarps) {
        const int base = t << 4;
        uint32_t Ah[3][4], Al[3][4], Ah3[2], Al3[2];
        float C[7][4];

        // ---- build layer-0 A fragments from x (K=16 exact, 1 k-step) ----
        {
            int r0 = base + g;     if (r0 > n - 1) r0 = n - 1;
            int r1 = base + g + 8; if (r1 > n - 1) r1 = n - 1;
            const float2* p0 = (const float2*)(x + (size_t)r0 * IN_DIM + t2);
            const float2* p1 = (const float2*)(x + (size_t)r1 * IN_DIM + t2);
            float2 v00 = p0[0], v01 = p0[4];
            float2 v10 = p1[0], v11 = p1[4];
            split2(v00.x, v00.y, Ah[0][0], Al[0][0]);
            split2(v10.x, v10.y, Ah[0][1], Al[0][1]);
            split2(v01.x, v01.y, Ah[0][2], Al[0][2]);
            split2(v11.x, v11.y, Ah[0][3], Al[0][3]);
        }
        layer_mma<1, false>(sm, sb, 0, Ah, Al, 0u, 0u, C, lane);

        // ---- 14 hidden layers (K = 50: 3x k16 + 1 merged k8 tail) ----
#pragma unroll 1
        for (int l = 1; l < NL; l++) {
            epilogue(C, Ah, Al, Ah3, Al3);
            uint32_t at0, at1;
            make_tail(Ah3, Al3, lane, at0, at1);
            layer_mma<3, true>(sm, sb, l, Ah, Al, at0, at1, C, lane);
        }

        // ---- output layer: 50 -> 4 (single n-tile, 3x k16 + 1 merged k8) ----
        epilogue(C, Ah, Al, Ah3, Al3);
        {
            uint32_t at0, at1;
            make_tail(Ah3, Al3, lane, at0, at1);
            float Co[4];
            float2 bv = *(const float2*)(sm + OFF_BO + t2 * 4);
            Co[0] = bv.x; Co[1] = bv.y; Co[2] = bv.x; Co[3] = bv.y;
            const uint32_t hibase = sb + OFF_WO;
            const uint32_t lobase = hibase + 1024;
            const uint32_t swz = (uint32_t)(ln << 4);
#pragma unroll
            for (int ks = 0; ks < 3; ks++) {
                const uint32_t xh = (uint32_t)((ks * 2 + (u & 1)) << 4) ^ swz;
                uint32_t w[2];
                ldsm2(w, hibase + (uint32_t)(ln * 128) + xh);
                mma_bf(Co, Ah[ks], w[0], w[1]);
                mma_bf(Co, Al[ks], w[0], w[1]);
                ldsm2(w, lobase + (uint32_t)(ln * 128) + xh);
                mma_bf(Co, Ah[ks], w[0], w[1]);
            }
            {
                const uint32_t x8 = (uint32_t)(96u ^ (uint32_t)(ln << 4));
                uint32_t w0;
                ldsm1(w0, hibase + (uint32_t)(ln * 128) + x8);
                mma_bf8(Co, at0, at1, w0);
            }
            if (t2 < OUT_DIM) {
                int r0 = base + g, r1 = base + g + 8;
                if (r0 < n) *(float2*)(out + (size_t)r0 * OUT_DIM + t2) = make_float2(Co[0], Co[1]);
                if (r1 < n) *(float2*)(out + (size_t)r1 * OUT_DIM + t2) = make_float2(Co[2], Co[3]);
            }
        }
    }
}

extern "C" void kernel_launch(void* const* d_in, const int* in_sizes, int n_in,
                              void* d_out, int out_size) {
    const float* x  = (const float*)d_in[0];
    const float* W0 = (const float*)d_in[1];
    const float* b0 = (const float*)d_in[2];
    const float* Wh = (const float*)d_in[3];
    const float* bh = (const float*)d_in[4];
    const float* Wo = (const float*)d_in[5];
    const float* bo = (const float*)d_in[6];
    float* out = (float*)d_out;

    int n = in_sizes[0] / IN_DIM;
    int ntiles = (n + 15) >> 4;

    int sms = 148;
    cudaDeviceGetAttribute(&sms, cudaDevAttrMultiProcessorCount, 0);

    cudaFuncSetAttribute(mlp_mma_kernel, cudaFuncAttributeMaxDynamicSharedMemorySize,
                         SMEM_BYTES);

    int nwarps = sms * WARPS;
    mlp_mma_kernel<<<sms, THREADS, SMEM_BYTES>>>(x, W0, b0, Wh, bh, Wo, bo, out,
                                                 n, ntiles, nwarps);
}

// round 7
// speedup vs baseline: 3.3951x; 1.0075x over previous
#include <cuda_runtime.h>
#include <cuda_bf16.h>
#include <cstdint>

#define IN_DIM   16
#define WIDTH    50
#define OUT_DIM  4
#define NL       15            // layer0 (16->50) + 14 hidden (50->50)
#define THREADS  384
#define WARPS    (THREADS/32)

// Weights in smem: per layer, hi+lo parts, each [56 rows][64 k] bf16,
// row stride 128B, 16B-chunk swizzled by (row&7).
// hi part chunk 6 (cols 48-55) holds the MERGED TAIL: [bh48 bh49 bh48 bh49 bl48 bl49 0 0]
#define SZ_PART   7168                    // 56*128
#define SZ_LAYER  (2*SZ_PART)             // 14336
#define OFF_WH    0                       // [15][2][56][64]
#define OFF_WO    (NL*SZ_LAYER)           // 215040: [2][8 rows][64]
#define OFF_BIAS  (OFF_WO + 2*1024)       // 217088: [15][56] f32
#define OFF_BO    (OFF_BIAS + NL*56*4)    // 220448: [8] f32
#define SMEM_BYTES (OFF_BO + 32)          // 220480

__device__ __forceinline__ uint32_t smem_u32(const void* p) {
    uint32_t a;
    asm("{ .reg .u64 t; cvta.to.shared.u64 t, %1; cvt.u32.u64 %0, t; }" : "=r"(a) : "l"(p));
    return a;
}
__device__ __forceinline__ void ldsm4(uint32_t* r, uint32_t a) {
    asm volatile("ldmatrix.sync.aligned.m8n8.x4.shared.b16 {%0,%1,%2,%3}, [%4];"
                 : "=r"(r[0]), "=r"(r[1]), "=r"(r[2]), "=r"(r[3]) : "r"(a));
}
__device__ __forceinline__ void ldsm2(uint32_t* r, uint32_t a) {
    asm volatile("ldmatrix.sync.aligned.m8n8.x2.shared.b16 {%0,%1}, [%2];"
                 : "=r"(r[0]), "=r"(r[1]) : "r"(a));
}
__device__ __forceinline__ void ldsm1(uint32_t& r, uint32_t a) {
    asm volatile("ldmatrix.sync.aligned.m8n8.x1.shared.b16 {%0}, [%1];"
                 : "=r"(r) : "r"(a));
}
__device__ __forceinline__ void mma_bf(float* c, const uint32_t* a, uint32_t b0, uint32_t b1) {
    asm("mma.sync.aligned.m16n8k16.row.col.f32.bf16.bf16.f32 "
        "{%0,%1,%2,%3}, {%4,%5,%6,%7}, {%8,%9}, {%0,%1,%2,%3};"
        : "+f"(c[0]), "+f"(c[1]), "+f"(c[2]), "+f"(c[3])
        : "r"(a[0]), "r"(a[1]), "r"(a[2]), "r"(a[3]), "r"(b0), "r"(b1));
}
__device__ __forceinline__ void mma_bf8(float* c, uint32_t a0, uint32_t a1, uint32_t b0) {
    asm("mma.sync.aligned.m16n8k8.row.col.f32.bf16.bf16.f32 "
        "{%0,%1,%2,%3}, {%4,%5}, {%6}, {%0,%1,%2,%3};"
        : "+f"(c[0]), "+f"(c[1]), "+f"(c[2]), "+f"(c[3])
        : "r"(a0), "r"(a1), "r"(b0));
}
// split two fp32 into packed bf16 hi + bf16 lo (residual)
__device__ __forceinline__ void split2(float a, float b, uint32_t& hi, uint32_t& lo) {
    __nv_bfloat162 t = __float22bfloat162_rn(make_float2(a, b));
    hi = *reinterpret_cast<uint32_t*>(&t);
    float fa = __uint_as_float(hi << 16);
    float fb = __uint_as_float(hi & 0xFFFF0000u);
    __nv_bfloat162 t2 = __float22bfloat162_rn(make_float2(a - fa, b - fb));
    lo = *reinterpret_cast<uint32_t*>(&t2);
}

// swizzled byte offset within one weight part for (row n, col k)
__device__ __host__ __forceinline__ uint32_t swoff(int n, int k) {
    return (uint32_t)(n * 128 + (((k >> 3) << 4) ^ ((n & 7) << 4)) + ((k & 7) << 1));
}

// Build the merged-tail A fragment: k-cols [ah|al|ah|0] from quad-lane-0's
// C[6] splits (cols 48,49). 4 shuffles + selects.
__device__ __forceinline__ void make_tail(const uint32_t Ah3[2], const uint32_t Al3[2],
                                          int lane, uint32_t& a0, uint32_t& a1) {
    const int src = lane & 28;
    uint32_t ah0 = __shfl_sync(0xFFFFFFFFu, Ah3[0], src);
    uint32_t ah1 = __shfl_sync(0xFFFFFFFFu, Ah3[1], src);
    uint32_t al0 = __shfl_sync(0xFFFFFFFFu, Al3[0], src);
    uint32_t al1 = __shfl_sync(0xFFFFFFFFu, Al3[1], src);
    const int t = lane & 3;
    a0 = (t == 3) ? 0u : (t == 1 ? al0 : ah0);
    a1 = (t == 3) ? 0u : (t == 1 ? al1 : ah1);
}

// Dual-tile MMA layer: C[2][7][4] += A[tile] * W^T; B fragments shared.
template <int NK16, bool TAIL>
__device__ __forceinline__ void layer_mma2(const char* sm, uint32_t sb, int layer,
                                           const uint32_t Ah[2][3][4], const uint32_t Al[2][3][4],
                                           const uint32_t at0[2], const uint32_t at1[2],
                                           float C[2][7][4], int lane) {
    const int t2 = (lane & 3) * 2;
    const int ln = lane & 7;
    const int u  = lane >> 3;
    const int nb = ((u >> 1) << 3) + ln;          // row-within-pair (x4 pattern)

    // bias init, shared between the two tiles
    const float* bias = (const float*)(sm + OFF_BIAS + layer * 224);
#pragma unroll
    for (int nt = 0; nt < 7; nt++) {
        float2 bv = *(const float2*)(bias + nt * 8 + t2);
#pragma unroll
        for (int tt = 0; tt < 2; tt++) {
            C[tt][nt][0] = bv.x; C[tt][nt][1] = bv.y;
            C[tt][nt][2] = bv.x; C[tt][nt][3] = bv.y;
        }
    }

    const uint32_t hibase = sb + OFF_WH + (uint32_t)layer * SZ_LAYER;
    const uint32_t lobase = hibase + SZ_PART;
    const uint32_t swz = (uint32_t)(ln << 4);

#pragma unroll
    for (int ks = 0; ks < NK16; ks++) {
        const uint32_t xh = (uint32_t)((ks * 2 + (u & 1)) << 4) ^ swz;
        uint32_t bf[14];
        // --- hi part ---
        ldsm4(bf + 0, hibase + (uint32_t)((0 * 16 + nb) * 128) + xh);
        ldsm4(bf + 4, hibase + (uint32_t)((1 * 16 + nb) * 128) + xh);
        ldsm4(bf + 8, hibase + (uint32_t)((2 * 16 + nb) * 128) + xh);
        ldsm2(bf + 12, hibase + (uint32_t)((48 + ln) * 128) + xh);
#pragma unroll
        for (int tt = 0; tt < 2; tt++)
#pragma unroll
            for (int nt = 0; nt < 7; nt++) mma_bf(C[tt][nt], Ah[tt][ks], bf[2*nt], bf[2*nt+1]);
#pragma unroll
        for (int tt = 0; tt < 2; tt++)
#pragma unroll
            for (int nt = 0; nt < 7; nt++) mma_bf(C[tt][nt], Al[tt][ks], bf[2*nt], bf[2*nt+1]);
        // --- lo part (times A-hi) ---
        ldsm4(bf + 0, lobase + (uint32_t)((0 * 16 + nb) * 128) + xh);
        ldsm4(bf + 4, lobase + (uint32_t)((1 * 16 + nb) * 128) + xh);
        ldsm4(bf + 8, lobase + (uint32_t)((2 * 16 + nb) * 128) + xh);
        ldsm2(bf + 12, lobase + (uint32_t)((48 + ln) * 128) + xh);
#pragma unroll
        for (int tt = 0; tt < 2; tt++)
#pragma unroll
            for (int nt = 0; nt < 7; nt++) mma_bf(C[tt][nt], Ah[tt][ks], bf[2*nt], bf[2*nt+1]);
    }

    if (TAIL) {
        // single merged k8 step (chunk 6 of hi part holds the mixed B tail)
        const uint32_t x8 = (uint32_t)(96u ^ (uint32_t)(ln << 4));
        uint32_t b8[8];
        ldsm4(b8 + 0, hibase + (uint32_t)(lane * 128) + x8);
        ldsm4(b8 + 4, hibase + (uint32_t)((32 + lane) * 128) + x8);
#pragma unroll
        for (int tt = 0; tt < 2; tt++)
#pragma unroll
            for (int nt = 0; nt < 7; nt++) mma_bf8(C[tt][nt], at0[tt], at1[tt], b8[nt]);
    }
}

// ReLU + convert C (7 n-tiles) into next layer's A fragments (3 k16 + tail pair)
__device__ __forceinline__ void epilogue(float C[7][4], uint32_t Ah[3][4], uint32_t Al[3][4],
                                         uint32_t* Ah3, uint32_t* Al3) {
#pragma unroll
    for (int nt = 0; nt < 7; nt++)
#pragma unroll
        for (int q = 0; q < 4; q++) C[nt][q] = fmaxf(C[nt][q], 0.f);
#pragma unroll
    for (int s = 0; s < 3; s++) {
        split2(C[2*s][0],   C[2*s][1],   Ah[s][0], Al[s][0]);
        split2(C[2*s][2],   C[2*s][3],   Ah[s][1], Al[s][1]);
        split2(C[2*s+1][0], C[2*s+1][1], Ah[s][2], Al[s][2]);
        split2(C[2*s+1][2], C[2*s+1][3], Ah[s][3], Al[s][3]);
    }
    split2(C[6][0], C[6][1], Ah3[0], Al3[0]);
    split2(C[6][2], C[6][3], Ah3[1], Al3[1]);
}

// build layer-0 A fragments for one tile from x
__device__ __forceinline__ void build_a0(const float* x, int n, int base, int g, int t2,
                                         uint32_t Ah[3][4], uint32_t Al[3][4]) {
    int r0 = base + g;     if (r0 > n - 1) r0 = n - 1;
    int r1 = base + g + 8; if (r1 > n - 1) r1 = n - 1;
    const float2* p0 = (const float2*)(x + (size_t)r0 * IN_DIM + t2);
    const float2* p1 = (const float2*)(x + (size_t)r1 * IN_DIM + t2);
    float2 v00 = p0[0], v01 = p0[4];
    float2 v10 = p1[0], v11 = p1[4];
    split2(v00.x, v00.y, Ah[0][0], Al[0][0]);
    split2(v10.x, v10.y, Ah[0][1], Al[0][1]);
    split2(v01.x, v01.y, Ah[0][2], Al[0][2]);
    split2(v11.x, v11.y, Ah[0][3], Al[0][3]);
}

__global__ __launch_bounds__(THREADS, 1)
void mlp_mma_kernel(const float* __restrict__ x,
                    const float* __restrict__ W0, const float* __restrict__ b0,
                    const float* __restrict__ Wh, const float* __restrict__ bh,
                    const float* __restrict__ Wo, const float* __restrict__ bo,
                    float* __restrict__ out, int n, int npairs, int nwarps) {
    extern __shared__ char sm[];
    const uint32_t sb = smem_u32(sm);
    const int tid  = threadIdx.x;
    const int wid  = tid >> 5;
    const int lane = tid & 31;

    // ---- stage weights: hi/lo bf16, zero-padded, swizzled; merged tail in hi chunk 6 ----
    for (int idx = tid; idx < NL * 56 * 64; idx += THREADS) {
        int l = idx / 3584;
        int r = idx - l * 3584;
        int nrow = r >> 6, k = r & 63;
        int Kreal = (l == 0) ? IN_DIM : WIDTH;
        __nv_bfloat16 hv, lv;
        if (k < 48) {
            float f = 0.f;
            if (nrow < WIDTH && k < Kreal)
                f = (l == 0) ? W0[nrow * IN_DIM + k] : Wh[((l - 1) * WIDTH + nrow) * WIDTH + k];
            hv = __float2bfloat16(f);
            lv = __float2bfloat16(f - __bfloat162float(hv));
        } else {
            int m = k - 48, p = m >> 1, c = m & 1;
            int kk = 48 + c;
            float f = 0.f;
            if (l > 0 && nrow < WIDTH && kk < Kreal)
                f = Wh[((l - 1) * WIDTH + nrow) * WIDTH + kk];
            __nv_bfloat16 fh = __float2bfloat16(f);
            __nv_bfloat16 fl = __float2bfloat16(f - __bfloat162float(fh));
            hv = (p < 2) ? fh : (p == 2 ? fl : __float2bfloat16(0.f));
            lv = __float2bfloat16(0.f);
        }
        uint32_t so = swoff(nrow, k);
        *(__nv_bfloat16*)(sm + OFF_WH + l * SZ_LAYER + so)           = hv;
        *(__nv_bfloat16*)(sm + OFF_WH + l * SZ_LAYER + SZ_PART + so) = lv;
    }
    for (int idx = tid; idx < 8 * 64; idx += THREADS) {
        int nrow = idx >> 6, k = idx & 63;
        __nv_bfloat16 hv, lv;
        if (k < 48) {
            float f = (nrow < OUT_DIM) ? Wo[nrow * WIDTH + k] : 0.f;
            hv = __float2bfloat16(f);
            lv = __float2bfloat16(f - __bfloat162float(hv));
        } else {
            int m = k - 48, p = m >> 1, c = m & 1;
            int kk = 48 + c;
            float f = (nrow < OUT_DIM && kk < WIDTH) ? Wo[nrow * WIDTH + kk] : 0.f;
            __nv_bfloat16 fh = __float2bfloat16(f);
            __nv_bfloat16 fl = __float2bfloat16(f - __bfloat162float(fh));
            hv = (p < 2) ? fh : (p == 2 ? fl : __float2bfloat16(0.f));
            lv = __float2bfloat16(0.f);
        }
        uint32_t so = swoff(nrow, k);
        *(__nv_bfloat16*)(sm + OFF_WO + so)        = hv;
        *(__nv_bfloat16*)(sm + OFF_WO + 1024 + so) = lv;
    }
    for (int idx = tid; idx < NL * 56; idx += THREADS) {
        int l = idx / 56, j = idx - l * 56;
        float f = 0.f;
        if (j < WIDTH) f = (l == 0) ? b0[j] : bh[(l - 1) * WIDTH + j];
        *(float*)(sm + OFF_BIAS + idx * 4) = f;
    }
    if (tid < 8) *(float*)(sm + OFF_BO + tid * 4) = (tid < OUT_DIM) ? bo[tid] : 0.f;
    __syncthreads();

    const int g  = lane >> 2;
    const int t2 = (lane & 3) * 2;
    const int ln = lane & 7;
    const int u  = lane >> 3;

    for (int tp = blockIdx.x * WARPS + wid; tp < npairs; tp += nwarps) {
        const int base0 = tp << 5;
        const int base1 = base0 + 16;
        uint32_t Ah[2][3][4], Al[2][3][4], Ah3[2][2], Al3[2][2];
        uint32_t at0[2], at1[2];
        float C[2][7][4];

        // ---- build layer-0 A fragments from x (K=16 exact, 1 k-step) ----
        build_a0(x, n, base0, g, t2, Ah[0], Al[0]);
        build_a0(x, n, base1, g, t2, Ah[1], Al[1]);
        at0[0] = at0[1] = at1[0] = at1[1] = 0u;
        layer_mma2<1, false>(sm, sb, 0, Ah, Al, at0, at1, C, lane);

        // ---- 14 hidden layers (K = 50: 3x k16 + 1 merged k8 tail) ----
#pragma unroll 1
        for (int l = 1; l < NL; l++) {
            epilogue(C[0], Ah[0], Al[0], Ah3[0], Al3[0]);
            epilogue(C[1], Ah[1], Al[1], Ah3[1], Al3[1]);
            make_tail(Ah3[0], Al3[0], lane, at0[0], at1[0]);
            make_tail(Ah3[1], Al3[1], lane, at0[1], at1[1]);
            layer_mma2<3, true>(sm, sb, l, Ah, Al, at0, at1, C, lane);
        }

        // ---- output layer: 50 -> 4 (single n-tile, shared weight frags) ----
        epilogue(C[0], Ah[0], Al[0], Ah3[0], Al3[0]);
        epilogue(C[1], Ah[1], Al[1], Ah3[1], Al3[1]);
        make_tail(Ah3[0], Al3[0], lane, at0[0], at1[0]);
        make_tail(Ah3[1], Al3[1], lane, at0[1], at1[1]);
        {
            float Co[2][4];
            float2 bv = *(const float2*)(sm + OFF_BO + t2 * 4);
#pragma unroll
            for (int tt = 0; tt < 2; tt++) {
                Co[tt][0] = bv.x; Co[tt][1] = bv.y; Co[tt][2] = bv.x; Co[tt][3] = bv.y;
            }
            const uint32_t hibase = sb + OFF_WO;
            const uint32_t lobase = hibase + 1024;
#pragma unroll
            for (int ks = 0; ks < 3; ks++) {
                const uint32_t xh = (uint32_t)((ks * 2 + (u & 1)) << 4) ^ (uint32_t)(ln << 4);
                uint32_t w[2];
                ldsm2(w, hibase + (uint32_t)(ln * 128) + xh);
                mma_bf(Co[0], Ah[0][ks], w[0], w[1]);
                mma_bf(Co[1], Ah[1][ks], w[0], w[1]);
                mma_bf(Co[0], Al[0][ks], w[0], w[1]);
                mma_bf(Co[1], Al[1][ks], w[0], w[1]);
                ldsm2(w, lobase + (uint32_t)(ln * 128) + xh);
                mma_bf(Co[0], Ah[0][ks], w[0], w[1]);
                mma_bf(Co[1], Ah[1][ks], w[0], w[1]);
            }
            {
                const uint32_t x8 = (uint32_t)(96u ^ (uint32_t)(ln << 4));
                uint32_t w0;
                ldsm1(w0, hibase + (uint32_t)(ln * 128) + x8);
                mma_bf8(Co[0], at0[0], at1[0], w0);
                mma_bf8(Co[1], at0[1], at1[1], w0);
            }
            if (t2 < OUT_DIM) {
#pragma unroll
                for (int tt = 0; tt < 2; tt++) {
                    int base = tt ? base1 : base0;
                    int r0 = base + g, r1 = base + g + 8;
                    if (r0 < n) *(float2*)(out + (size_t)r0 * OUT_DIM + t2) = make_float2(Co[tt][0], Co[tt][1]);
                    if (r1 < n) *(float2*)(out + (size_t)r1 * OUT_DIM + t2) = make_float2(Co[tt][2], Co[tt][3]);
                }
            }
        }
    }
}

extern "C" void kernel_launch(void* const* d_in, const int* in_sizes, int n_in,
                              void* d_out, int out_size) {
    const float* x  = (const float*)d_in[0];
    const float* W0 = (const float*)d_in[1];
    const float* b0 = (const float*)d_in[2];
    const float* Wh = (const float*)d_in[3];
    const float* bh = (const float*)d_in[4];
    const float* Wo = (const float*)d_in[5];
    const float* bo = (const float*)d_in[6];
    float* out = (float*)d_out;

    int n = in_sizes[0] / IN_DIM;
    int npairs = (n + 31) >> 5;

    int sms = 148;
    cudaDeviceGetAttribute(&sms, cudaDevAttrMultiProcessorCount, 0);

    cudaFuncSetAttribute(mlp_mma_kernel, cudaFuncAttributeMaxDynamicSharedMemorySize,
                         SMEM_BYTES);

    int nwarps = sms * WARPS;
    mlp_mma_kernel<<<sms, THREADS, SMEM_BYTES>>>(x, W0, b0, Wh, bh, Wo, bo, out,
                                                 n, npairs, nwarps);
}